// round 3
// baseline (speedup 1.0000x reference)
#include <cuda_runtime.h>
#include <cuda_bf16.h>
#include <cstdint>

// Problem constants (fixed by the dataset)
#define N_NODES    100000
#define N_FEAT     512
#define N_HID      256
// E comes from in_sizes[1] at launch.

// Scratch for h = x @ W^T + b : [N_NODES, N_HID] fp32 (102.4 MB, static device global)
__device__ float g_h[(size_t)N_NODES * N_HID];

// ---------------------------------------------------------------------------
// Kernel 1: SGEMM with bias.  C[M,N] = A[M,K] * B[N,K]^T + bias[N]
// A = x (row-major, K contiguous), B = W (row-major, K contiguous) -> NT gemm.
// Classic 128x128x8 tile, 256 threads, 8x8 per-thread microtile.
// ---------------------------------------------------------------------------
#define BM 128
#define BN 128
#define BK 8
#define TM 8
#define TN 8

__global__ __launch_bounds__(256, 2)
void gemm_bias_kernel(const float* __restrict__ A,
                      const float* __restrict__ B,
                      const float* __restrict__ bias,
                      float* __restrict__ C,
                      int M, int N, int K)
{
    __shared__ float As[BK][BM];
    __shared__ float Bs[BK][BN];

    const int tid = threadIdx.x;              // 0..255
    const int block_row = blockIdx.x * BM;
    const int block_col = blockIdx.y * BN;

    // Global-load mapping: 256 threads * float4 = 1024 floats = one 128x8 tile.
    const int ld_row  = tid >> 1;             // 0..127
    const int ld_col4 = (tid & 1) * 4;        // 0 or 4

    // Compute mapping: 16x16 thread grid, each 8x8.
    const int ty = (tid >> 4) * TM;           // 0..120
    const int tx = (tid & 15) * TN;           // 0..120

    float acc[TM][TN];
#pragma unroll
    for (int i = 0; i < TM; i++)
#pragma unroll
        for (int j = 0; j < TN; j++) acc[i][j] = 0.f;

    for (int k0 = 0; k0 < K; k0 += BK) {
        // Load A tile (guard M tail)
        float4 av = make_float4(0.f, 0.f, 0.f, 0.f);
        {
            int gr = block_row + ld_row;
            if (gr < M)
                av = *(const float4*)(A + (size_t)gr * K + k0 + ld_col4);
        }
        As[ld_col4 + 0][ld_row] = av.x;
        As[ld_col4 + 1][ld_row] = av.y;
        As[ld_col4 + 2][ld_row] = av.z;
        As[ld_col4 + 3][ld_row] = av.w;

        // Load B tile (N=256 exactly covered by 2 column blocks, no guard)
        float4 bv = *(const float4*)(B + (size_t)(block_col + ld_row) * K + k0 + ld_col4);
        Bs[ld_col4 + 0][ld_row] = bv.x;
        Bs[ld_col4 + 1][ld_row] = bv.y;
        Bs[ld_col4 + 2][ld_row] = bv.z;
        Bs[ld_col4 + 3][ld_row] = bv.w;

        __syncthreads();

#pragma unroll
        for (int k = 0; k < BK; k++) {
            float ar[TM], br[TN];
#pragma unroll
            for (int i = 0; i < TM; i++) ar[i] = As[k][ty + i];
#pragma unroll
            for (int j = 0; j < TN; j++) br[j] = Bs[k][tx + j];
#pragma unroll
            for (int i = 0; i < TM; i++)
#pragma unroll
                for (int j = 0; j < TN; j++)
                    acc[i][j] = fmaf(ar[i], br[j], acc[i][j]);
        }
        __syncthreads();
    }

    // Epilogue: add bias, store (vectorized float4 along N)
#pragma unroll
    for (int i = 0; i < TM; i++) {
        int row = block_row + ty + i;
        if (row >= M) continue;
#pragma unroll
        for (int j = 0; j < TN; j += 4) {
            int col = block_col + tx + j;
            float4 v;
            v.x = acc[i][j + 0] + bias[col + 0];
            v.y = acc[i][j + 1] + bias[col + 1];
            v.z = acc[i][j + 2] + bias[col + 2];
            v.w = acc[i][j + 3] + bias[col + 3];
            *(float4*)(C + (size_t)row * N + col) = v;
        }
    }
}

// ---------------------------------------------------------------------------
// Kernel 2: edge-parallel SpMM scatter.
// One warp per edge: gather h[col] (256 f32 = 64 float4, 2 per lane), scale by
// val, red.global.add.v4.f32 into out[row].
// ---------------------------------------------------------------------------
__device__ __forceinline__ void red_add_v4(float* addr, float4 v)
{
    asm volatile("red.global.add.v4.f32 [%0], {%1, %2, %3, %4};"
                 :: "l"(addr), "f"(v.x), "f"(v.y), "f"(v.z), "f"(v.w)
                 : "memory");
}

__global__ __launch_bounds__(256)
void spmm_scatter_kernel(const int*   __restrict__ rows,
                         const int*   __restrict__ cols,
                         const float* __restrict__ vals,
                         float*       __restrict__ out,
                         int E)
{
    const int warp_id = (blockIdx.x * blockDim.x + threadIdx.x) >> 5;
    const int lane    = threadIdx.x & 31;
    if (warp_id >= E) return;

    const int   r = rows[warp_id];
    const int   c = cols[warp_id];
    const float v = vals[warp_id];

    const float4* src = (const float4*)(g_h + (size_t)c * N_HID);
    float* dst = out + (size_t)r * N_HID;

    float4 a = __ldg(&src[lane]);
    float4 b = __ldg(&src[lane + 32]);

    a.x *= v; a.y *= v; a.z *= v; a.w *= v;
    b.x *= v; b.y *= v; b.z *= v; b.w *= v;

    red_add_v4(dst + lane * 4,        a);
    red_add_v4(dst + (lane + 32) * 4, b);
}

// ---------------------------------------------------------------------------
// Kernel 3: in-place PReLU over the aggregated output.
// ---------------------------------------------------------------------------
__global__ __launch_bounds__(256)
void prelu_kernel(float* __restrict__ out, const float* __restrict__ alpha_p,
                  int n4)
{
    const float alpha = *alpha_p;
    int i = blockIdx.x * blockDim.x + threadIdx.x;
    if (i >= n4) return;
    float4 v = ((float4*)out)[i];
    v.x = v.x >= 0.f ? v.x : alpha * v.x;
    v.y = v.y >= 0.f ? v.y : alpha * v.y;
    v.z = v.z >= 0.f ? v.z : alpha * v.z;
    v.w = v.w >= 0.f ? v.w : alpha * v.w;
    ((float4*)out)[i] = v;
}

// ---------------------------------------------------------------------------
// Launch
// ---------------------------------------------------------------------------
extern "C" void kernel_launch(void* const* d_in, const int* in_sizes, int n_in,
                              void* d_out, int out_size)
{
    const float* x     = (const float*)d_in[0];   // [1, N_NODES, N_FEAT]
    const int*   rows  = (const int*)  d_in[1];   // [E]
    const int*   cols  = (const int*)  d_in[2];   // [E]
    const float* vals  = (const float*)d_in[3];   // [E]
    const float* W     = (const float*)d_in[4];   // [N_HID, N_FEAT]
    const float* b     = (const float*)d_in[5];   // [N_HID]
    const float* alpha = (const float*)d_in[6];   // scalar

    float* out = (float*)d_out;                   // [1, N_NODES, N_HID]
    const int E = in_sizes[1];

    float* h;
    cudaGetSymbolAddress((void**)&h, g_h);

    // 1) h = x @ W^T + b
    dim3 ggrid((N_NODES + BM - 1) / BM, N_HID / BN);
    gemm_bias_kernel<<<ggrid, 256>>>(x, W, b, h, N_NODES, N_HID, N_FEAT);

    // 2) zero the output accumulator (d_out is poisoned)
    cudaMemsetAsync(d_out, 0, (size_t)out_size * sizeof(float));

    // 3) edge scatter: one warp per edge, 8 warps per block
    int nblocks = (E + 7) / 8;
    spmm_scatter_kernel<<<nblocks, 256>>>(rows, cols, vals, out, E);

    // 4) PReLU in place
    int n4 = out_size / 4;
    prelu_kernel<<<(n4 + 255) / 256, 256>>>(out, alpha, n4);
}

// round 6
// speedup vs baseline: 1.2928x; 1.2928x over previous
#include <cuda_runtime.h>
#include <cuda_bf16.h>
#include <cstdint>

// Problem constants (fixed by the dataset)
#define N_NODES    100000
#define N_FEAT     512
#define N_HID      256

// ---------------------------------------------------------------------------
// Static device scratch (no allocations allowed)
// ---------------------------------------------------------------------------
__device__ float g_h[(size_t)N_NODES * N_HID];                          // 102.4 MB
__device__ __align__(16) __nv_bfloat16 g_xhi[(size_t)N_NODES * N_FEAT]; // 102.4 MB
__device__ __align__(16) __nv_bfloat16 g_xlo[(size_t)N_NODES * N_FEAT]; // 102.4 MB
__device__ __align__(16) __nv_bfloat16 g_whi[(size_t)N_HID * N_FEAT];   // 256 KB
__device__ __align__(16) __nv_bfloat16 g_wlo[(size_t)N_HID * N_FEAT];   // 256 KB

// ---------------------------------------------------------------------------
// Baseline-PTX helpers (all plain sm_80+ instructions; no arch-'a' features)
// ---------------------------------------------------------------------------
__device__ __forceinline__ uint32_t smem_to_u32(const void* smem_ptr) {
    uint32_t addr;
    asm("{ .reg .u64 tmp; cvta.to.shared.u64 tmp, %1; cvt.u32.u64 %0, tmp; }"
        : "=r"(addr) : "l"(smem_ptr));
    return addr;
}

__device__ __forceinline__ void cp_async16(uint32_t saddr, const void* gptr) {
    asm volatile("cp.async.cg.shared.global [%0], [%1], 16;"
                 :: "r"(saddr), "l"(gptr));
}
#define CP_COMMIT()  asm volatile("cp.async.commit_group;")
#define CP_WAIT(N)   asm volatile("cp.async.wait_group %0;" :: "n"(N))

// ldmatrix x4 (non-trans): 4x 8x8 b16 matrices
__device__ __forceinline__ void ldm_x4(uint32_t* r, uint32_t addr) {
    asm volatile("ldmatrix.sync.aligned.m8n8.x4.shared.b16 {%0,%1,%2,%3}, [%4];"
                 : "=r"(r[0]), "=r"(r[1]), "=r"(r[2]), "=r"(r[3]) : "r"(addr));
}

// HMMA m16n8k16 bf16 -> fp32, accumulate in place
__device__ __forceinline__ void mma16816(float* d, const uint32_t* a,
                                         const uint32_t* b) {
    asm volatile(
        "mma.sync.aligned.m16n8k16.row.col.f32.bf16.bf16.f32 "
        "{%0,%1,%2,%3}, {%4,%5,%6,%7}, {%8,%9}, {%0,%1,%2,%3};"
        : "+f"(d[0]), "+f"(d[1]), "+f"(d[2]), "+f"(d[3])
        : "r"(a[0]), "r"(a[1]), "r"(a[2]), "r"(a[3]),
          "r"(b[0]), "r"(b[1]));
}

// ---------------------------------------------------------------------------
// Kernel A: fp32 -> (bf16 hi, bf16 lo) split
// ---------------------------------------------------------------------------
__global__ __launch_bounds__(256)
void split_bf16_kernel(const float* __restrict__ src,
                       __nv_bfloat16* __restrict__ hi,
                       __nv_bfloat16* __restrict__ lo, int n4)
{
    int i = blockIdx.x * blockDim.x + threadIdx.x;
    if (i >= n4) return;
    float4 v = ((const float4*)src)[i];
    __nv_bfloat16 h0 = __float2bfloat16(v.x);
    __nv_bfloat16 h1 = __float2bfloat16(v.y);
    __nv_bfloat16 h2 = __float2bfloat16(v.z);
    __nv_bfloat16 h3 = __float2bfloat16(v.w);
    __nv_bfloat16 l0 = __float2bfloat16(v.x - __bfloat162float(h0));
    __nv_bfloat16 l1 = __float2bfloat16(v.y - __bfloat162float(h1));
    __nv_bfloat16 l2 = __float2bfloat16(v.z - __bfloat162float(h2));
    __nv_bfloat16 l3 = __float2bfloat16(v.w - __bfloat162float(h3));
    ((__nv_bfloat162*)hi)[2 * i]     = __halves2bfloat162(h0, h1);
    ((__nv_bfloat162*)hi)[2 * i + 1] = __halves2bfloat162(h2, h3);
    ((__nv_bfloat162*)lo)[2 * i]     = __halves2bfloat162(l0, l1);
    ((__nv_bfloat162*)lo)[2 * i + 1] = __halves2bfloat162(l2, l3);
}

// ---------------------------------------------------------------------------
// Kernel B: mma.sync bf16 GEMM (3-term hi/lo) with bias.
// C[M,256] = Ahi*Bhi^T + Ahi*Blo^T + Alo*Bhi^T + bias
// Tile 128x128x32, 256 threads (2x4 warps, each 64x32), cp.async double buffer.
// ---------------------------------------------------------------------------
#define BM 128
#define BN 128
#define BK 32
#define SSTRIDE 80                  // smem row stride bytes (40 bf16, padded)
#define TILE_B  (128 * SSTRIDE)     // 10240 B per 128x32 bf16 tile
#define BUF_B   (4 * TILE_B)        // Ahi,Alo,Bhi,Blo per buffer = 40960 B
#define AHI_O   0
#define ALO_O   TILE_B
#define BHI_O   (2 * TILE_B)
#define BLO_O   (3 * TILE_B)
#define GEMM_SMEM (2 * BUF_B)       // 81920 B
#define NCHUNK  (N_FEAT / BK)       // 16

__global__ __launch_bounds__(256, 1)
void gemm_mma_kernel(const __nv_bfloat16* __restrict__ Ahi,
                     const __nv_bfloat16* __restrict__ Alo,
                     const __nv_bfloat16* __restrict__ Bhi,
                     const __nv_bfloat16* __restrict__ Blo,
                     const float* __restrict__ bias,
                     float* __restrict__ C, int M)
{
    extern __shared__ __align__(128) char smem[];
    const uint32_t sb = smem_to_u32(smem);

    const int tid    = threadIdx.x;
    const int lane   = tid & 31;
    const int wid    = tid >> 5;
    const int warp_m = wid >> 2;          // 0..1  (64-row slab)
    const int warp_n = wid & 3;           // 0..3  (32-col slab)
    const int tile_row  = blockIdx.x * BM;
    const int block_col = blockIdx.y * BN;

    float acc[4][4][4];
#pragma unroll
    for (int a = 0; a < 4; a++)
#pragma unroll
        for (int b = 0; b < 4; b++)
#pragma unroll
            for (int c = 0; c < 4; c++) acc[a][b][c] = 0.f;

    // ---- gmem -> smem stage (8 cp.async of 16B per thread per chunk) ----
    auto issue = [&](int c) {
        const int buf = c & 1;
        const uint32_t b = sb + buf * BUF_B;
#pragma unroll
        for (int t = 0; t < 2; t++) {
            int idx = t * 256 + tid;          // 0..511
            int r = idx >> 2, s = idx & 3;    // row 0..127, 16B seg 0..3
            uint32_t so = r * SSTRIDE + s * 16;
            int gr = tile_row + r; if (gr >= M) gr = M - 1;
            size_t goA = (size_t)gr * N_FEAT + c * BK + s * 8;
            cp_async16(b + AHI_O + so, Ahi + goA);
            cp_async16(b + ALO_O + so, Alo + goA);
            int gn = block_col + r;
            size_t goB = (size_t)gn * N_FEAT + c * BK + s * 8;
            cp_async16(b + BHI_O + so, Bhi + goB);
            cp_async16(b + BLO_O + so, Blo + goB);
        }
        CP_COMMIT();
    };

    // ---- compute one 32-wide K chunk from buffer `buf` ----
    auto compute = [&](int buf) {
        const uint32_t b = sb + buf * BUF_B;
        const int arow  = warp_m * 64 + (lane & 15);
        const int brow  = warp_n * 32 + (lane & 7) + ((lane >> 4) << 3);
#pragma unroll
        for (int kk = 0; kk < 2; kk++) {
            const int k0 = kk * 16;
            const int acol2 = (k0 + ((lane >> 4) << 3)) * 2;
            const int bcol2 = (k0 + (((lane >> 3) & 1) << 3)) * 2;
#pragma unroll
            for (int term = 0; term < 3; term++) {
                const uint32_t aoff = (term == 2) ? ALO_O : AHI_O;
                const uint32_t boff = (term == 1) ? BLO_O : BHI_O;
                uint32_t aF[4][4], bF[4][2];
#pragma unroll
                for (int mt = 0; mt < 4; mt++)
                    ldm_x4(aF[mt],
                           b + aoff + (uint32_t)(arow + mt * 16) * SSTRIDE + acol2);
#pragma unroll
                for (int h = 0; h < 2; h++) {
                    uint32_t r[4];
                    ldm_x4(r, b + boff + (uint32_t)(brow + h * 16) * SSTRIDE + bcol2);
                    bF[h * 2][0]     = r[0]; bF[h * 2][1]     = r[1];
                    bF[h * 2 + 1][0] = r[2]; bF[h * 2 + 1][1] = r[3];
                }
#pragma unroll
                for (int mt = 0; mt < 4; mt++)
#pragma unroll
                    for (int nt = 0; nt < 4; nt++)
                        mma16816(acc[mt][nt], aF[mt], bF[nt]);
            }
        }
    };

    // ---- double-buffered pipeline ----
    issue(0);
    for (int c = 0; c < NCHUNK; c++) {
        if (c + 1 < NCHUNK) { issue(c + 1); CP_WAIT(1); }
        else                { CP_WAIT(0); }
        __syncthreads();
        compute(c & 1);
        __syncthreads();
    }

    // ---- epilogue: bias add + store ----
    const int g  = lane >> 2;
    const int tg = lane & 3;
#pragma unroll
    for (int mt = 0; mt < 4; mt++) {
        const int r0 = tile_row + warp_m * 64 + mt * 16 + g;
#pragma unroll
        for (int half = 0; half < 2; half++) {
            const int row = r0 + half * 8;
            if (row >= M) continue;
            float* cp = C + (size_t)row * N_HID;
#pragma unroll
            for (int nt = 0; nt < 4; nt++) {
                const int col = block_col + warp_n * 32 + nt * 8 + tg * 2;
                float2 o;
                o.x = acc[mt][nt][half * 2 + 0] + __ldg(bias + col);
                o.y = acc[mt][nt][half * 2 + 1] + __ldg(bias + col + 1);
                *(float2*)(cp + col) = o;
            }
        }
    }
}

// ---------------------------------------------------------------------------
// Kernel C: edge scatter over ONE feature half (128 floats) for L2 locality.
// ---------------------------------------------------------------------------
__device__ __forceinline__ void red_add_v4(float* addr, float4 v)
{
    asm volatile("red.global.add.v4.f32 [%0], {%1, %2, %3, %4};"
                 :: "l"(addr), "f"(v.x), "f"(v.y), "f"(v.z), "f"(v.w)
                 : "memory");
}

__global__ __launch_bounds__(256)
void spmm_scatter_half(const int*   __restrict__ rows,
                       const int*   __restrict__ cols,
                       const float* __restrict__ vals,
                       float*       __restrict__ out,
                       int E, int half)
{
    const int warp_id = (blockIdx.x * blockDim.x + threadIdx.x) >> 5;
    const int lane    = threadIdx.x & 31;
    if (warp_id >= E) return;

    const int   r = rows[warp_id];
    const int   c = cols[warp_id];
    const float v = vals[warp_id];

    const float4* src = (const float4*)(g_h + (size_t)c * N_HID + half * 128);
    float*        dst = out + (size_t)r * N_HID + half * 128;

    float4 a = __ldg(&src[lane]);
    a.x *= v; a.y *= v; a.z *= v; a.w *= v;
    red_add_v4(dst + lane * 4, a);
}

// ---------------------------------------------------------------------------
// Kernel D: in-place PReLU.
// ---------------------------------------------------------------------------
__global__ __launch_bounds__(256)
void prelu_kernel(float* __restrict__ out, const float* __restrict__ alpha_p,
                  int n4)
{
    const float alpha = *alpha_p;
    int i = blockIdx.x * blockDim.x + threadIdx.x;
    if (i >= n4) return;
    float4 v = ((float4*)out)[i];
    v.x = v.x >= 0.f ? v.x : alpha * v.x;
    v.y = v.y >= 0.f ? v.y : alpha * v.y;
    v.z = v.z >= 0.f ? v.z : alpha * v.z;
    v.w = v.w >= 0.f ? v.w : alpha * v.w;
    ((float4*)out)[i] = v;
}

// ---------------------------------------------------------------------------
// Launch
// ---------------------------------------------------------------------------
extern "C" void kernel_launch(void* const* d_in, const int* in_sizes, int n_in,
                              void* d_out, int out_size)
{
    const float* x     = (const float*)d_in[0];
    const int*   rows  = (const int*)  d_in[1];
    const int*   cols  = (const int*)  d_in[2];
    const float* vals  = (const float*)d_in[3];
    const float* W     = (const float*)d_in[4];
    const float* b     = (const float*)d_in[5];
    const float* alpha = (const float*)d_in[6];

    float* out = (float*)d_out;
    const int E = in_sizes[1];

    float *h; __nv_bfloat16 *xhi, *xlo, *whi, *wlo;
    cudaGetSymbolAddress((void**)&h,   g_h);
    cudaGetSymbolAddress((void**)&xhi, g_xhi);
    cudaGetSymbolAddress((void**)&xlo, g_xlo);
    cudaGetSymbolAddress((void**)&whi, g_whi);
    cudaGetSymbolAddress((void**)&wlo, g_wlo);

    // 1) bf16 hi/lo splits
    {
        int n4x = (N_NODES * N_FEAT) / 4;
        split_bf16_kernel<<<(n4x + 255) / 256, 256>>>(x, xhi, xlo, n4x);
        int n4w = (N_HID * N_FEAT) / 4;
        split_bf16_kernel<<<(n4w + 255) / 256, 256>>>(W, whi, wlo, n4w);
    }

    // 2) tensor-core (HMMA) GEMM with bias -> g_h
    cudaFuncSetAttribute(gemm_mma_kernel,
                         cudaFuncAttributeMaxDynamicSharedMemorySize, GEMM_SMEM);
    dim3 ggrid((N_NODES + BM - 1) / BM, N_HID / BN);
    gemm_mma_kernel<<<ggrid, 256, GEMM_SMEM>>>(xhi, xlo, whi, wlo, b, h, N_NODES);

    // 3) zero output accumulator
    cudaMemsetAsync(d_out, 0, (size_t)out_size * sizeof(float));

    // 4) edge scatter, two sequential feature-half passes (L2 locality)
    int nblocks = (E + 7) / 8;
    spmm_scatter_half<<<nblocks, 256>>>(rows, cols, vals, out, E, 0);
    spmm_scatter_half<<<nblocks, 256>>>(rows, cols, vals, out, E, 1);

    // 5) PReLU in place
    int n4 = out_size / 4;
    prelu_kernel<<<(n4 + 255) / 256, 256>>>(out, alpha, n4);
}

// round 7
// speedup vs baseline: 2.3045x; 1.7826x over previous
#include <cuda_runtime.h>
#include <cuda_bf16.h>
#include <cstdint>

// Problem constants (fixed by the dataset)
#define N_NODES    100000
#define N_FEAT     512
#define N_HID      256
#define MAX_E      3276800      // dataset E = 3,200,000 (+ margin)

// ---------------------------------------------------------------------------
// Static device scratch (no allocations allowed)
// ---------------------------------------------------------------------------
__device__ float g_h[(size_t)N_NODES * N_HID];                          // 102.4 MB
__device__ __align__(16) __nv_bfloat16 g_xhi[(size_t)N_NODES * N_FEAT]; // 102.4 MB
__device__ __align__(16) __nv_bfloat16 g_xlo[(size_t)N_NODES * N_FEAT]; // 102.4 MB
__device__ __align__(16) __nv_bfloat16 g_whi[(size_t)N_HID * N_FEAT];   // 256 KB
__device__ __align__(16) __nv_bfloat16 g_wlo[(size_t)N_HID * N_FEAT];   // 256 KB

// CSR build scratch
__device__ int   g_cnt[N_NODES];
__device__ int   g_tmp[N_NODES];
__device__ int   g_rowptr[N_NODES + 1];
__device__ int   g_blocksum[128];
__device__ int   g_scol[MAX_E];
__device__ float g_sval[MAX_E];

#define SCAN_BLK 1024
#define NB_SCAN  ((N_NODES + SCAN_BLK - 1) / SCAN_BLK)   // 98

// ---------------------------------------------------------------------------
// Baseline-PTX helpers (plain sm_80+; the harness compiles for compute_103
// without the 'a' suffix, so no tcgen05/arch-specific features)
// ---------------------------------------------------------------------------
__device__ __forceinline__ uint32_t smem_to_u32(const void* smem_ptr) {
    uint32_t addr;
    asm("{ .reg .u64 tmp; cvta.to.shared.u64 tmp, %1; cvt.u32.u64 %0, tmp; }"
        : "=r"(addr) : "l"(smem_ptr));
    return addr;
}

__device__ __forceinline__ void cp_async16(uint32_t saddr, const void* gptr) {
    asm volatile("cp.async.cg.shared.global [%0], [%1], 16;"
                 :: "r"(saddr), "l"(gptr));
}
#define CP_COMMIT()  asm volatile("cp.async.commit_group;")
#define CP_WAIT(N)   asm volatile("cp.async.wait_group %0;" :: "n"(N))

__device__ __forceinline__ void ldm_x4(uint32_t* r, uint32_t addr) {
    asm volatile("ldmatrix.sync.aligned.m8n8.x4.shared.b16 {%0,%1,%2,%3}, [%4];"
                 : "=r"(r[0]), "=r"(r[1]), "=r"(r[2]), "=r"(r[3]) : "r"(addr));
}

__device__ __forceinline__ void mma16816(float* d, const uint32_t* a,
                                         const uint32_t* b) {
    asm volatile(
        "mma.sync.aligned.m16n8k16.row.col.f32.bf16.bf16.f32 "
        "{%0,%1,%2,%3}, {%4,%5,%6,%7}, {%8,%9}, {%0,%1,%2,%3};"
        : "+f"(d[0]), "+f"(d[1]), "+f"(d[2]), "+f"(d[3])
        : "r"(a[0]), "r"(a[1]), "r"(a[2]), "r"(a[3]),
          "r"(b[0]), "r"(b[1]));
}

// ---------------------------------------------------------------------------
// Kernel A: fp32 -> (bf16 hi, bf16 lo) split
// ---------------------------------------------------------------------------
__global__ __launch_bounds__(256)
void split_bf16_kernel(const float* __restrict__ src,
                       __nv_bfloat16* __restrict__ hi,
                       __nv_bfloat16* __restrict__ lo, int n4)
{
    int i = blockIdx.x * blockDim.x + threadIdx.x;
    if (i >= n4) return;
    float4 v = ((const float4*)src)[i];
    __nv_bfloat16 h0 = __float2bfloat16(v.x);
    __nv_bfloat16 h1 = __float2bfloat16(v.y);
    __nv_bfloat16 h2 = __float2bfloat16(v.z);
    __nv_bfloat16 h3 = __float2bfloat16(v.w);
    __nv_bfloat16 l0 = __float2bfloat16(v.x - __bfloat162float(h0));
    __nv_bfloat16 l1 = __float2bfloat16(v.y - __bfloat162float(h1));
    __nv_bfloat16 l2 = __float2bfloat16(v.z - __bfloat162float(h2));
    __nv_bfloat16 l3 = __float2bfloat16(v.w - __bfloat162float(h3));
    ((__nv_bfloat162*)hi)[2 * i]     = __halves2bfloat162(h0, h1);
    ((__nv_bfloat162*)hi)[2 * i + 1] = __halves2bfloat162(h2, h3);
    ((__nv_bfloat162*)lo)[2 * i]     = __halves2bfloat162(l0, l1);
    ((__nv_bfloat162*)lo)[2 * i + 1] = __halves2bfloat162(l2, l3);
}

// ---------------------------------------------------------------------------
// Kernel B: mma.sync bf16 GEMM (3-term hi/lo) with bias.  (unchanged, works)
// ---------------------------------------------------------------------------
#define BM 128
#define BN 128
#define BK 32
#define SSTRIDE 80
#define TILE_B  (128 * SSTRIDE)
#define BUF_B   (4 * TILE_B)
#define AHI_O   0
#define ALO_O   TILE_B
#define BHI_O   (2 * TILE_B)
#define BLO_O   (3 * TILE_B)
#define GEMM_SMEM (2 * BUF_B)
#define NCHUNK  (N_FEAT / BK)

__global__ __launch_bounds__(256, 1)
void gemm_mma_kernel(const __nv_bfloat16* __restrict__ Ahi,
                     const __nv_bfloat16* __restrict__ Alo,
                     const __nv_bfloat16* __restrict__ Bhi,
                     const __nv_bfloat16* __restrict__ Blo,
                     const float* __restrict__ bias,
                     float* __restrict__ C, int M)
{
    extern __shared__ __align__(128) char smem[];
    const uint32_t sb = smem_to_u32(smem);

    const int tid    = threadIdx.x;
    const int lane   = tid & 31;
    const int wid    = tid >> 5;
    const int warp_m = wid >> 2;
    const int warp_n = wid & 3;
    const int tile_row  = blockIdx.x * BM;
    const int block_col = blockIdx.y * BN;

    float acc[4][4][4];
#pragma unroll
    for (int a = 0; a < 4; a++)
#pragma unroll
        for (int b = 0; b < 4; b++)
#pragma unroll
            for (int c = 0; c < 4; c++) acc[a][b][c] = 0.f;

    auto issue = [&](int c) {
        const int buf = c & 1;
        const uint32_t b = sb + buf * BUF_B;
#pragma unroll
        for (int t = 0; t < 2; t++) {
            int idx = t * 256 + tid;
            int r = idx >> 2, s = idx & 3;
            uint32_t so = r * SSTRIDE + s * 16;
            int gr = tile_row + r; if (gr >= M) gr = M - 1;
            size_t goA = (size_t)gr * N_FEAT + c * BK + s * 8;
            cp_async16(b + AHI_O + so, Ahi + goA);
            cp_async16(b + ALO_O + so, Alo + goA);
            int gn = block_col + r;
            size_t goB = (size_t)gn * N_FEAT + c * BK + s * 8;
            cp_async16(b + BHI_O + so, Bhi + goB);
            cp_async16(b + BLO_O + so, Blo + goB);
        }
        CP_COMMIT();
    };

    auto compute = [&](int buf) {
        const uint32_t b = sb + buf * BUF_B;
        const int arow  = warp_m * 64 + (lane & 15);
        const int brow  = warp_n * 32 + (lane & 7) + ((lane >> 4) << 3);
#pragma unroll
        for (int kk = 0; kk < 2; kk++) {
            const int k0 = kk * 16;
            const int acol2 = (k0 + ((lane >> 4) << 3)) * 2;
            const int bcol2 = (k0 + (((lane >> 3) & 1) << 3)) * 2;
#pragma unroll
            for (int term = 0; term < 3; term++) {
                const uint32_t aoff = (term == 2) ? ALO_O : AHI_O;
                const uint32_t boff = (term == 1) ? BLO_O : BHI_O;
                uint32_t aF[4][4], bF[4][2];
#pragma unroll
                for (int mt = 0; mt < 4; mt++)
                    ldm_x4(aF[mt],
                           b + aoff + (uint32_t)(arow + mt * 16) * SSTRIDE + acol2);
#pragma unroll
                for (int h = 0; h < 2; h++) {
                    uint32_t r[4];
                    ldm_x4(r, b + boff + (uint32_t)(brow + h * 16) * SSTRIDE + bcol2);
                    bF[h * 2][0]     = r[0]; bF[h * 2][1]     = r[1];
                    bF[h * 2 + 1][0] = r[2]; bF[h * 2 + 1][1] = r[3];
                }
#pragma unroll
                for (int mt = 0; mt < 4; mt++)
#pragma unroll
                    for (int nt = 0; nt < 4; nt++)
                        mma16816(acc[mt][nt], aF[mt], bF[nt]);
            }
        }
    };

    issue(0);
    for (int c = 0; c < NCHUNK; c++) {
        if (c + 1 < NCHUNK) { issue(c + 1); CP_WAIT(1); }
        else                { CP_WAIT(0); }
        __syncthreads();
        compute(c & 1);
        __syncthreads();
    }

    const int g  = lane >> 2;
    const int tg = lane & 3;
#pragma unroll
    for (int mt = 0; mt < 4; mt++) {
        const int r0 = tile_row + warp_m * 64 + mt * 16 + g;
#pragma unroll
        for (int half = 0; half < 2; half++) {
            const int row = r0 + half * 8;
            if (row >= M) continue;
            float* cp = C + (size_t)row * N_HID;
#pragma unroll
            for (int nt = 0; nt < 4; nt++) {
                const int col = block_col + warp_n * 32 + nt * 8 + tg * 2;
                float2 o;
                o.x = acc[mt][nt][half * 2 + 0] + __ldg(bias + col);
                o.y = acc[mt][nt][half * 2 + 1] + __ldg(bias + col + 1);
                *(float2*)(cp + col) = o;
            }
        }
    }
}

// ---------------------------------------------------------------------------
// CSR build: count -> 2-level exclusive scan -> positioned scatter
// ---------------------------------------------------------------------------
__global__ __launch_bounds__(256)
void csr_count_kernel(const int* __restrict__ rows, int E)
{
    int e = blockIdx.x * blockDim.x + threadIdx.x;
    if (e < E) atomicAdd(&g_cnt[rows[e]], 1);
}

__global__ __launch_bounds__(SCAN_BLK)
void scan1_kernel()
{
    __shared__ int s[SCAN_BLK];
    const int tid = threadIdx.x;
    const int i = blockIdx.x * SCAN_BLK + tid;
    int v = (i < N_NODES) ? g_cnt[i] : 0;
    s[tid] = v;
    __syncthreads();
#pragma unroll
    for (int off = 1; off < SCAN_BLK; off <<= 1) {
        int t = (tid >= off) ? s[tid - off] : 0;
        __syncthreads();
        s[tid] += t;
        __syncthreads();
    }
    if (i < N_NODES) g_rowptr[i] = s[tid] - v;   // exclusive
    if (tid == SCAN_BLK - 1) g_blocksum[blockIdx.x] = s[tid];
}

__global__ __launch_bounds__(128)
void scan2_kernel()
{
    __shared__ int s[128];
    const int tid = threadIdx.x;
    int v = (tid < NB_SCAN) ? g_blocksum[tid] : 0;
    s[tid] = v;
    __syncthreads();
#pragma unroll
    for (int off = 1; off < 128; off <<= 1) {
        int t = (tid >= off) ? s[tid - off] : 0;
        __syncthreads();
        s[tid] += t;
        __syncthreads();
    }
    if (tid < NB_SCAN) g_blocksum[tid] = s[tid] - v;  // exclusive
}

__global__ __launch_bounds__(SCAN_BLK)
void scan3_kernel(int E)
{
    const int i = blockIdx.x * SCAN_BLK + threadIdx.x;
    if (i < N_NODES) g_rowptr[i] += g_blocksum[blockIdx.x];
    if (i == 0) g_rowptr[N_NODES] = E;
}

__global__ __launch_bounds__(256)
void csr_scatter_kernel(const int* __restrict__ rows,
                        const int* __restrict__ cols,
                        const float* __restrict__ vals, int E)
{
    int e = blockIdx.x * blockDim.x + threadIdx.x;
    if (e >= E) return;
    int r = rows[e];
    int pos = g_rowptr[r] + atomicAdd(&g_tmp[r], 1);
    g_scol[pos] = cols[e];
    g_sval[pos] = vals[e];
}

// ---------------------------------------------------------------------------
// Kernel C: CSR SpMM + fused PReLU. One warp per output row; register
// accumulation (2 float4/lane = 256 features), streaming write-once stores.
// ---------------------------------------------------------------------------
__device__ __forceinline__ void stcs_v4(float* p, float4 v) {
    asm volatile("st.global.cs.v4.f32 [%0], {%1,%2,%3,%4};"
                 :: "l"(p), "f"(v.x), "f"(v.y), "f"(v.z), "f"(v.w) : "memory");
}

__global__ __launch_bounds__(256)
void spmm_csr_prelu(float* __restrict__ out,
                    const float* __restrict__ alpha_p)
{
    const int warp = (blockIdx.x * blockDim.x + threadIdx.x) >> 5;
    const int lane = threadIdx.x & 31;
    if (warp >= N_NODES) return;

    const int start = g_rowptr[warp];
    const int end   = g_rowptr[warp + 1];

    float4 acc0 = make_float4(0.f, 0.f, 0.f, 0.f);
    float4 acc1 = make_float4(0.f, 0.f, 0.f, 0.f);

    int e = start;
    for (; e + 1 < end; e += 2) {
        int   c0 = __ldcs(&g_scol[e]);
        float v0 = __ldcs(&g_sval[e]);
        int   c1 = __ldcs(&g_scol[e + 1]);
        float v1 = __ldcs(&g_sval[e + 1]);
        const float4* s0 = (const float4*)(g_h + (size_t)c0 * N_HID);
        const float4* s1 = (const float4*)(g_h + (size_t)c1 * N_HID);
        float4 a0 = __ldg(&s0[lane]);
        float4 b0 = __ldg(&s0[lane + 32]);
        float4 a1 = __ldg(&s1[lane]);
        float4 b1 = __ldg(&s1[lane + 32]);
        acc0.x = fmaf(v0, a0.x, acc0.x); acc0.y = fmaf(v0, a0.y, acc0.y);
        acc0.z = fmaf(v0, a0.z, acc0.z); acc0.w = fmaf(v0, a0.w, acc0.w);
        acc1.x = fmaf(v0, b0.x, acc1.x); acc1.y = fmaf(v0, b0.y, acc1.y);
        acc1.z = fmaf(v0, b0.z, acc1.z); acc1.w = fmaf(v0, b0.w, acc1.w);
        acc0.x = fmaf(v1, a1.x, acc0.x); acc0.y = fmaf(v1, a1.y, acc0.y);
        acc0.z = fmaf(v1, a1.z, acc0.z); acc0.w = fmaf(v1, a1.w, acc0.w);
        acc1.x = fmaf(v1, b1.x, acc1.x); acc1.y = fmaf(v1, b1.y, acc1.y);
        acc1.z = fmaf(v1, b1.z, acc1.z); acc1.w = fmaf(v1, b1.w, acc1.w);
    }
    if (e < end) {
        int   c0 = __ldcs(&g_scol[e]);
        float v0 = __ldcs(&g_sval[e]);
        const float4* s0 = (const float4*)(g_h + (size_t)c0 * N_HID);
        float4 a0 = __ldg(&s0[lane]);
        float4 b0 = __ldg(&s0[lane + 32]);
        acc0.x = fmaf(v0, a0.x, acc0.x); acc0.y = fmaf(v0, a0.y, acc0.y);
        acc0.z = fmaf(v0, a0.z, acc0.z); acc0.w = fmaf(v0, a0.w, acc0.w);
        acc1.x = fmaf(v0, b0.x, acc1.x); acc1.y = fmaf(v0, b0.y, acc1.y);
        acc1.z = fmaf(v0, b0.z, acc1.z); acc1.w = fmaf(v0, b0.w, acc1.w);
    }

    const float alpha = __ldg(alpha_p);
    acc0.x = acc0.x >= 0.f ? acc0.x : alpha * acc0.x;
    acc0.y = acc0.y >= 0.f ? acc0.y : alpha * acc0.y;
    acc0.z = acc0.z >= 0.f ? acc0.z : alpha * acc0.z;
    acc0.w = acc0.w >= 0.f ? acc0.w : alpha * acc0.w;
    acc1.x = acc1.x >= 0.f ? acc1.x : alpha * acc1.x;
    acc1.y = acc1.y >= 0.f ? acc1.y : alpha * acc1.y;
    acc1.z = acc1.z >= 0.f ? acc1.z : alpha * acc1.z;
    acc1.w = acc1.w >= 0.f ? acc1.w : alpha * acc1.w;

    float* dst = out + (size_t)warp * N_HID;
    stcs_v4(dst + lane * 4,        acc0);
    stcs_v4(dst + (lane + 32) * 4, acc1);
}

// ---------------------------------------------------------------------------
// Launch
// ---------------------------------------------------------------------------
extern "C" void kernel_launch(void* const* d_in, const int* in_sizes, int n_in,
                              void* d_out, int out_size)
{
    const float* x     = (const float*)d_in[0];
    const int*   rows  = (const int*)  d_in[1];
    const int*   cols  = (const int*)  d_in[2];
    const float* vals  = (const float*)d_in[3];
    const float* W     = (const float*)d_in[4];
    const float* b     = (const float*)d_in[5];
    const float* alpha = (const float*)d_in[6];

    float* out = (float*)d_out;
    const int E = in_sizes[1];

    float *h; __nv_bfloat16 *xhi, *xlo, *whi, *wlo;
    cudaGetSymbolAddress((void**)&h,   g_h);
    cudaGetSymbolAddress((void**)&xhi, g_xhi);
    cudaGetSymbolAddress((void**)&xlo, g_xlo);
    cudaGetSymbolAddress((void**)&whi, g_whi);
    cudaGetSymbolAddress((void**)&wlo, g_wlo);

    int *cntp, *tmpp;
    cudaGetSymbolAddress((void**)&cntp, g_cnt);
    cudaGetSymbolAddress((void**)&tmpp, g_tmp);

    // --- CSR build (independent of GEMM) ---
    cudaMemsetAsync(cntp, 0, N_NODES * sizeof(int));
    cudaMemsetAsync(tmpp, 0, N_NODES * sizeof(int));
    csr_count_kernel<<<(E + 255) / 256, 256>>>(rows, E);
    scan1_kernel<<<NB_SCAN, SCAN_BLK>>>();
    scan2_kernel<<<1, 128>>>();
    scan3_kernel<<<NB_SCAN, SCAN_BLK>>>(E);
    csr_scatter_kernel<<<(E + 255) / 256, 256>>>(rows, cols, vals, E);

    // --- bf16 hi/lo splits ---
    {
        int n4x = (N_NODES * N_FEAT) / 4;
        split_bf16_kernel<<<(n4x + 255) / 256, 256>>>(x, xhi, xlo, n4x);
        int n4w = (N_HID * N_FEAT) / 4;
        split_bf16_kernel<<<(n4w + 255) / 256, 256>>>(W, whi, wlo, n4w);
    }

    // --- HMMA GEMM with bias -> g_h ---
    cudaFuncSetAttribute(gemm_mma_kernel,
                         cudaFuncAttributeMaxDynamicSharedMemorySize, GEMM_SMEM);
    dim3 ggrid((N_NODES + BM - 1) / BM, N_HID / BN);
    gemm_mma_kernel<<<ggrid, 256, GEMM_SMEM>>>(xhi, xlo, whi, wlo, b, h, N_NODES);

    // --- CSR SpMM + fused PReLU (atomic-free, write-once) ---
    int nwarps_blocks = (N_NODES * 32 + 255) / 256;
    spmm_csr_prelu<<<nwarps_blocks, 256>>>(out, alpha);
}

// round 8
// speedup vs baseline: 3.1862x; 1.3826x over previous
#include <cuda_runtime.h>
#include <cuda_bf16.h>
#include <cuda_fp16.h>
#include <cstdint>

// Problem constants (fixed by the dataset)
#define N_NODES    100000
#define N_FEAT     512
#define N_HID      256
#define MAX_E      3276800      // dataset E = 3,200,000 (+ margin)

// ---------------------------------------------------------------------------
// Static device scratch (no allocations allowed)
// ---------------------------------------------------------------------------
__device__ float g_h[(size_t)N_NODES * N_HID];                      // 102.4 MB
__device__ __align__(16) __half g_wh[(size_t)N_HID * N_FEAT];       // 256 KB

// CSR build scratch
__device__ int  g_cnt[N_NODES];
__device__ int  g_tmp[N_NODES];
__device__ int  g_rowptr[N_NODES + 1];
__device__ int  g_blocksum[128];
__device__ __align__(8) int2 g_sedge[MAX_E];   // {col, val-as-int}

#define SCAN_BLK 1024
#define NB_SCAN  ((N_NODES + SCAN_BLK - 1) / SCAN_BLK)   // 98

// ---------------------------------------------------------------------------
// Baseline-PTX helpers (plain sm_80+; harness targets compute_103 w/o 'a')
// ---------------------------------------------------------------------------
__device__ __forceinline__ uint32_t smem_to_u32(const void* smem_ptr) {
    uint32_t addr;
    asm("{ .reg .u64 tmp; cvta.to.shared.u64 tmp, %1; cvt.u32.u64 %0, tmp; }"
        : "=r"(addr) : "l"(smem_ptr));
    return addr;
}

__device__ __forceinline__ void cp_async16(uint32_t saddr, const void* gptr) {
    asm volatile("cp.async.cg.shared.global [%0], [%1], 16;"
                 :: "r"(saddr), "l"(gptr));
}
#define CP_COMMIT()  asm volatile("cp.async.commit_group;")
#define CP_WAIT(N)   asm volatile("cp.async.wait_group %0;" :: "n"(N))

__device__ __forceinline__ void ldm_x4(uint32_t* r, uint32_t addr) {
    asm volatile("ldmatrix.sync.aligned.m8n8.x4.shared.b16 {%0,%1,%2,%3}, [%4];"
                 : "=r"(r[0]), "=r"(r[1]), "=r"(r[2]), "=r"(r[3]) : "r"(addr));
}

// HMMA m16n8k16 fp16 -> fp32, accumulate in place
__device__ __forceinline__ void mma16816(float* d, const uint32_t* a,
                                         const uint32_t* b) {
    asm volatile(
        "mma.sync.aligned.m16n8k16.row.col.f32.f16.f16.f32 "
        "{%0,%1,%2,%3}, {%4,%5,%6,%7}, {%8,%9}, {%0,%1,%2,%3};"
        : "+f"(d[0]), "+f"(d[1]), "+f"(d[2]), "+f"(d[3])
        : "r"(a[0]), "r"(a[1]), "r"(a[2]), "r"(a[3]),
          "r"(b[0]), "r"(b[1]));
}

__device__ __forceinline__ uint32_t pack_h2(float a, float b) {
    __half2 h = __floats2half2_rn(a, b);
    return *reinterpret_cast<uint32_t*>(&h);
}

// ---------------------------------------------------------------------------
// Kernel A: W fp32 -> fp16 convert (tiny: 128K elements)
// ---------------------------------------------------------------------------
__global__ __launch_bounds__(256)
void w_half_kernel(const float* __restrict__ src, __half* __restrict__ dst,
                   int n4)
{
    int i = blockIdx.x * blockDim.x + threadIdx.x;
    if (i >= n4) return;
    float4 v = ((const float4*)src)[i];
    uint2 o;
    o.x = pack_h2(v.x, v.y);
    o.y = pack_h2(v.z, v.w);
    ((uint2*)dst)[i] = o;
}

// ---------------------------------------------------------------------------
// Kernel B: mma.sync fp16 GEMM (single term) with bias.
// C[M,256] = half(A) * half(W)^T + bias,  fp32 accumulate.
// Tile 128x128x32, 256 threads (2x4 warps, each 64x32).
// A converted in-kernel: LDG float4 (reg double buffer) -> cvt -> STS.
// B (W fp16) via cp.async double buffer.
// ---------------------------------------------------------------------------
#define BM 128
#define BN 128
#define BK 32
#define SSTRIDE 80                  // smem row stride bytes (32 fp16 + pad)
#define TILE_B  (128 * SSTRIDE)     // 10240 B
#define A_O     0
#define B_O     TILE_B
#define BUF_B   (2 * TILE_B)        // 20480 B
#define GEMM_SMEM (2 * BUF_B)       // 40960 B
#define NCHUNK  (N_FEAT / BK)       // 16

__global__ __launch_bounds__(256, 1)
void gemm_mma_kernel(const float* __restrict__ A,
                     const __half* __restrict__ Bh,
                     const float* __restrict__ bias,
                     float* __restrict__ C, int M)
{
    extern __shared__ __align__(128) char smem[];
    const uint32_t sb = smem_to_u32(smem);

    const int tid    = threadIdx.x;
    const int lane   = tid & 31;
    const int wid    = tid >> 5;
    const int warp_m = wid >> 2;          // 0..1
    const int warp_n = wid & 3;           // 0..3
    const int tile_row  = blockIdx.x * BM;
    const int block_col = blockIdx.y * BN;

    // A-load mapping: idx = i*256+tid, i 0..3 ; row = idx>>3, seg = idx&7
    // (8 threads cover one 128B row -> fully coalesced)
    const int a_seg = tid & 7;
    const int a_r0  = tid >> 3;           // rows a_r0 + 32*i

    float acc[4][4][4];
#pragma unroll
    for (int a = 0; a < 4; a++)
#pragma unroll
        for (int b = 0; b < 4; b++)
#pragma unroll
            for (int c = 0; c < 4; c++) acc[a][b][c] = 0.f;

    float4 aPre[4];

    auto ldg_a = [&](int c) {
#pragma unroll
        for (int i = 0; i < 4; i++) {
            int gr = tile_row + a_r0 + 32 * i;
            if (gr >= M) gr = M - 1;
            aPre[i] = __ldg((const float4*)(A + (size_t)gr * N_FEAT
                                            + c * BK + a_seg * 4));
        }
    };
    auto sts_a = [&](int buf) {
        const uint32_t b = sb + buf * BUF_B + A_O;
#pragma unroll
        for (int i = 0; i < 4; i++) {
            uint2 o;
            o.x = pack_h2(aPre[i].x, aPre[i].y);
            o.y = pack_h2(aPre[i].z, aPre[i].w);
            *(uint2*)(smem + buf * BUF_B + A_O
                      + (a_r0 + 32 * i) * SSTRIDE + a_seg * 8) = o;
        }
        (void)b;
    };
    auto issue_b = [&](int c) {
        const uint32_t b = sb + (c & 1) * BUF_B + B_O;
#pragma unroll
        for (int t = 0; t < 2; t++) {
            int idx = t * 256 + tid;          // 0..511
            int r = idx >> 2, s = idx & 3;    // row 0..127, 16B seg 0..3
            size_t go = (size_t)(block_col + r) * N_FEAT + c * BK + s * 8;
            cp_async16(b + r * SSTRIDE + s * 16, Bh + go);
        }
        CP_COMMIT();
    };

    auto compute = [&](int buf) {
        const uint32_t base = sb + buf * BUF_B;
        const int arow  = warp_m * 64 + (lane & 15);
        const int brow  = warp_n * 32 + (lane & 7) + ((lane >> 4) << 3);
#pragma unroll
        for (int kk = 0; kk < 2; kk++) {
            const int k0 = kk * 16;
            const int acol2 = (k0 + ((lane >> 4) << 3)) * 2;
            const int bcol2 = (k0 + (((lane >> 3) & 1) << 3)) * 2;
            uint32_t aF[4][4], bF[4][2];
#pragma unroll
            for (int mt = 0; mt < 4; mt++)
                ldm_x4(aF[mt], base + A_O
                       + (uint32_t)(arow + mt * 16) * SSTRIDE + acol2);
#pragma unroll
            for (int h = 0; h < 2; h++) {
                uint32_t r[4];
                ldm_x4(r, base + B_O
                       + (uint32_t)(brow + h * 16) * SSTRIDE + bcol2);
                bF[h * 2][0]     = r[0]; bF[h * 2][1]     = r[1];
                bF[h * 2 + 1][0] = r[2]; bF[h * 2 + 1][1] = r[3];
            }
#pragma unroll
            for (int mt = 0; mt < 4; mt++)
#pragma unroll
                for (int nt = 0; nt < 4; nt++)
                    mma16816(acc[mt][nt], aF[mt], bF[nt]);
        }
    };

    // ---- pipeline prologue ----
    ldg_a(0);
    sts_a(0);
    issue_b(0);

    for (int c = 0; c < NCHUNK; c++) {
        if (c + 1 < NCHUNK) {
            ldg_a(c + 1);           // overlap LDG latency with compute below
            issue_b(c + 1);
            CP_WAIT(1);
        } else {
            CP_WAIT(0);
        }
        __syncthreads();            // A STS + B cp.async for chunk c visible
        compute(c & 1);
        __syncthreads();            // done reading buf c
        if (c + 1 < NCHUNK)
            sts_a((c + 1) & 1);     // fill other buffer's A region
    }

    // ---- epilogue: bias add + store ----
    const int g  = lane >> 2;
    const int tg = lane & 3;
#pragma unroll
    for (int mt = 0; mt < 4; mt++) {
        const int r0 = tile_row + warp_m * 64 + mt * 16 + g;
#pragma unroll
        for (int half = 0; half < 2; half++) {
            const int row = r0 + half * 8;
            if (row >= M) continue;
            float* cp = C + (size_t)row * N_HID;
#pragma unroll
            for (int nt = 0; nt < 4; nt++) {
                const int col = block_col + warp_n * 32 + nt * 8 + tg * 2;
                float2 o;
                o.x = acc[mt][nt][half * 2 + 0] + __ldg(bias + col);
                o.y = acc[mt][nt][half * 2 + 1] + __ldg(bias + col + 1);
                *(float2*)(cp + col) = o;
            }
        }
    }
}

// ---------------------------------------------------------------------------
// CSR build: count -> 2-level exclusive scan -> positioned scatter
// ---------------------------------------------------------------------------
__global__ __launch_bounds__(256)
void csr_count_kernel(const int* __restrict__ rows, int E)
{
    int e = blockIdx.x * blockDim.x + threadIdx.x;
    if (e < E) atomicAdd(&g_cnt[rows[e]], 1);
}

__global__ __launch_bounds__(SCAN_BLK)
void scan1_kernel()
{
    __shared__ int s[SCAN_BLK];
    const int tid = threadIdx.x;
    const int i = blockIdx.x * SCAN_BLK + tid;
    int v = (i < N_NODES) ? g_cnt[i] : 0;
    s[tid] = v;
    __syncthreads();
#pragma unroll
    for (int off = 1; off < SCAN_BLK; off <<= 1) {
        int t = (tid >= off) ? s[tid - off] : 0;
        __syncthreads();
        s[tid] += t;
        __syncthreads();
    }
    if (i < N_NODES) g_rowptr[i] = s[tid] - v;   // exclusive
    if (tid == SCAN_BLK - 1) g_blocksum[blockIdx.x] = s[tid];
}

__global__ __launch_bounds__(128)
void scan2_kernel()
{
    __shared__ int s[128];
    const int tid = threadIdx.x;
    int v = (tid < NB_SCAN) ? g_blocksum[tid] : 0;
    s[tid] = v;
    __syncthreads();
#pragma unroll
    for (int off = 1; off < 128; off <<= 1) {
        int t = (tid >= off) ? s[tid - off] : 0;
        __syncthreads();
        s[tid] += t;
        __syncthreads();
    }
    if (tid < NB_SCAN) g_blocksum[tid] = s[tid] - v;  // exclusive
}

__global__ __launch_bounds__(SCAN_BLK)
void scan3_kernel(int E)
{
    const int i = blockIdx.x * SCAN_BLK + threadIdx.x;
    if (i < N_NODES) g_rowptr[i] += g_blocksum[blockIdx.x];
    if (i == 0) g_rowptr[N_NODES] = E;
}

__global__ __launch_bounds__(256)
void csr_scatter_kernel(const int* __restrict__ rows,
                        const int* __restrict__ cols,
                        const float* __restrict__ vals, int E)
{
    int e = blockIdx.x * blockDim.x + threadIdx.x;
    if (e >= E) return;
    int r = rows[e];
    int pos = g_rowptr[r] + atomicAdd(&g_tmp[r], 1);
    g_sedge[pos] = make_int2(cols[e], __float_as_int(vals[e]));
}

// ---------------------------------------------------------------------------
// Kernel C: CSR SpMM + fused PReLU. One warp per output row; register
// accumulation (2 float4/lane = 256 features), streaming write-once stores.
// ---------------------------------------------------------------------------
__device__ __forceinline__ void stcs_v4(float* p, float4 v) {
    asm volatile("st.global.cs.v4.f32 [%0], {%1,%2,%3,%4};"
                 :: "l"(p), "f"(v.x), "f"(v.y), "f"(v.z), "f"(v.w) : "memory");
}

__global__ __launch_bounds__(256)
void spmm_csr_prelu(float* __restrict__ out,
                    const float* __restrict__ alpha_p)
{
    const int warp = (blockIdx.x * blockDim.x + threadIdx.x) >> 5;
    const int lane = threadIdx.x & 31;
    if (warp >= N_NODES) return;

    const int start = g_rowptr[warp];
    const int end   = g_rowptr[warp + 1];

    float4 acc0 = make_float4(0.f, 0.f, 0.f, 0.f);
    float4 acc1 = make_float4(0.f, 0.f, 0.f, 0.f);

    int e = start;
    for (; e + 1 < end; e += 2) {
        int2 e0 = __ldcs(&g_sedge[e]);
        int2 e1 = __ldcs(&g_sedge[e + 1]);
        const float v0 = __int_as_float(e0.y);
        const float v1 = __int_as_float(e1.y);
        const float4* s0 = (const float4*)(g_h + (size_t)e0.x * N_HID);
        const float4* s1 = (const float4*)(g_h + (size_t)e1.x * N_HID);
        float4 a0 = __ldg(&s0[lane]);
        float4 b0 = __ldg(&s0[lane + 32]);
        float4 a1 = __ldg(&s1[lane]);
        float4 b1 = __ldg(&s1[lane + 32]);
        acc0.x = fmaf(v0, a0.x, acc0.x); acc0.y = fmaf(v0, a0.y, acc0.y);
        acc0.z = fmaf(v0, a0.z, acc0.z); acc0.w = fmaf(v0, a0.w, acc0.w);
        acc1.x = fmaf(v0, b0.x, acc1.x); acc1.y = fmaf(v0, b0.y, acc1.y);
        acc1.z = fmaf(v0, b0.z, acc1.z); acc1.w = fmaf(v0, b0.w, acc1.w);
        acc0.x = fmaf(v1, a1.x, acc0.x); acc0.y = fmaf(v1, a1.y, acc0.y);
        acc0.z = fmaf(v1, a1.z, acc0.z); acc0.w = fmaf(v1, a1.w, acc0.w);
        acc1.x = fmaf(v1, b1.x, acc1.x); acc1.y = fmaf(v1, b1.y, acc1.y);
        acc1.z = fmaf(v1, b1.z, acc1.z); acc1.w = fmaf(v1, b1.w, acc1.w);
    }
    if (e < end) {
        int2 e0 = __ldcs(&g_sedge[e]);
        const float v0 = __int_as_float(e0.y);
        const float4* s0 = (const float4*)(g_h + (size_t)e0.x * N_HID);
        float4 a0 = __ldg(&s0[lane]);
        float4 b0 = __ldg(&s0[lane + 32]);
        acc0.x = fmaf(v0, a0.x, acc0.x); acc0.y = fmaf(v0, a0.y, acc0.y);
        acc0.z = fmaf(v0, a0.z, acc0.z); acc0.w = fmaf(v0, a0.w, acc0.w);
        acc1.x = fmaf(v0, b0.x, acc1.x); acc1.y = fmaf(v0, b0.y, acc1.y);
        acc1.z = fmaf(v0, b0.z, acc1.z); acc1.w = fmaf(v0, b0.w, acc1.w);
    }

    const float alpha = __ldg(alpha_p);
    acc0.x = acc0.x >= 0.f ? acc0.x : alpha * acc0.x;
    acc0.y = acc0.y >= 0.f ? acc0.y : alpha * acc0.y;
    acc0.z = acc0.z >= 0.f ? acc0.z : alpha * acc0.z;
    acc0.w = acc0.w >= 0.f ? acc0.w : alpha * acc0.w;
    acc1.x = acc1.x >= 0.f ? acc1.x : alpha * acc1.x;
    acc1.y = acc1.y >= 0.f ? acc1.y : alpha * acc1.y;
    acc1.z = acc1.z >= 0.f ? acc1.z : alpha * acc1.z;
    acc1.w = acc1.w >= 0.f ? acc1.w : alpha * acc1.w;

    float* dst = out + (size_t)warp * N_HID;
    stcs_v4(dst + lane * 4,        acc0);
    stcs_v4(dst + (lane + 32) * 4, acc1);
}

// ---------------------------------------------------------------------------
// Launch
// ---------------------------------------------------------------------------
extern "C" void kernel_launch(void* const* d_in, const int* in_sizes, int n_in,
                              void* d_out, int out_size)
{
    const float* x     = (const float*)d_in[0];
    const int*   rows  = (const int*)  d_in[1];
    const int*   cols  = (const int*)  d_in[2];
    const float* vals  = (const float*)d_in[3];
    const float* W     = (const float*)d_in[4];
    const float* b     = (const float*)d_in[5];
    const float* alpha = (const float*)d_in[6];

    float* out = (float*)d_out;
    const int E = in_sizes[1];

    float *h; __half *wh;
    cudaGetSymbolAddress((void**)&h,  g_h);
    cudaGetSymbolAddress((void**)&wh, g_wh);

    int *cntp, *tmpp;
    cudaGetSymbolAddress((void**)&cntp, g_cnt);
    cudaGetSymbolAddress((void**)&tmpp, g_tmp);

    // --- CSR build (independent of GEMM) ---
    cudaMemsetAsync(cntp, 0, N_NODES * sizeof(int));
    cudaMemsetAsync(tmpp, 0, N_NODES * sizeof(int));
    csr_count_kernel<<<(E + 255) / 256, 256>>>(rows, E);
    scan1_kernel<<<NB_SCAN, SCAN_BLK>>>();
    scan2_kernel<<<1, 128>>>();
    scan3_kernel<<<NB_SCAN, SCAN_BLK>>>(E);
    csr_scatter_kernel<<<(E + 255) / 256, 256>>>(rows, cols, vals, E);

    // --- W fp16 convert (tiny) ---
    {
        int n4w = (N_HID * N_FEAT) / 4;
        w_half_kernel<<<(n4w + 255) / 256, 256>>>(W, wh, n4w);
    }

    // --- fp16 HMMA GEMM with bias -> g_h (A converted in-kernel) ---
    cudaFuncSetAttribute(gemm_mma_kernel,
                         cudaFuncAttributeMaxDynamicSharedMemorySize, GEMM_SMEM);
    dim3 ggrid((N_NODES + BM - 1) / BM, N_HID / BN);
    gemm_mma_kernel<<<ggrid, 256, GEMM_SMEM>>>(x, wh, b, h, N_NODES);

    // --- CSR SpMM + fused PReLU (atomic-free, write-once) ---
    int nwarps_blocks = (N_NODES * 32 + 255) / 256;
    spmm_csr_prelu<<<nwarps_blocks, 256>>>(out, alpha);
}

// round 9
// speedup vs baseline: 5.1207x; 1.6071x over previous
#include <cuda_runtime.h>
#include <cuda_bf16.h>
#include <cuda_fp16.h>
#include <cstdint>

// Problem constants (fixed by the dataset)
#define N_NODES    100000
#define N_FEAT     512
#define N_HID      256
#define MAX_E      3276800      // dataset E = 3,200,000 (+ margin)

// ---------------------------------------------------------------------------
// Static device scratch (no allocations allowed)
// ---------------------------------------------------------------------------
__device__ __align__(16) __half g_hh[(size_t)N_NODES * N_HID];      // 51.2 MB
__device__ __align__(16) __half g_wh[(size_t)N_HID * N_FEAT];       // 256 KB

// CSR build scratch
__device__ int  g_cnt[N_NODES];
__device__ int  g_tmp[N_NODES];
__device__ int  g_rowptr[N_NODES + 1];
__device__ int  g_blocksum[128];
__device__ __align__(8) int2 g_sedge[MAX_E];   // {col, val-as-int}

#define SCAN_BLK 1024
#define NB_SCAN  ((N_NODES + SCAN_BLK - 1) / SCAN_BLK)   // 98

// ---------------------------------------------------------------------------
// Baseline-PTX helpers (plain sm_80+; harness targets compute_103 w/o 'a')
// ---------------------------------------------------------------------------
__device__ __forceinline__ uint32_t smem_to_u32(const void* smem_ptr) {
    uint32_t addr;
    asm("{ .reg .u64 tmp; cvta.to.shared.u64 tmp, %1; cvt.u32.u64 %0, tmp; }"
        : "=r"(addr) : "l"(smem_ptr));
    return addr;
}

__device__ __forceinline__ void cp_async16(uint32_t saddr, const void* gptr) {
    asm volatile("cp.async.cg.shared.global [%0], [%1], 16;"
                 :: "r"(saddr), "l"(gptr));
}
#define CP_COMMIT()  asm volatile("cp.async.commit_group;")
#define CP_WAIT(N)   asm volatile("cp.async.wait_group %0;" :: "n"(N))

__device__ __forceinline__ void ldm_x4(uint32_t* r, uint32_t addr) {
    asm volatile("ldmatrix.sync.aligned.m8n8.x4.shared.b16 {%0,%1,%2,%3}, [%4];"
                 : "=r"(r[0]), "=r"(r[1]), "=r"(r[2]), "=r"(r[3]) : "r"(addr));
}

// HMMA m16n8k16 fp16 -> fp32, accumulate in place
__device__ __forceinline__ void mma16816(float* d, const uint32_t* a,
                                         const uint32_t* b) {
    asm volatile(
        "mma.sync.aligned.m16n8k16.row.col.f32.f16.f16.f32 "
        "{%0,%1,%2,%3}, {%4,%5,%6,%7}, {%8,%9}, {%0,%1,%2,%3};"
        : "+f"(d[0]), "+f"(d[1]), "+f"(d[2]), "+f"(d[3])
        : "r"(a[0]), "r"(a[1]), "r"(a[2]), "r"(a[3]),
          "r"(b[0]), "r"(b[1]));
}

__device__ __forceinline__ uint32_t pack_h2(float a, float b) {
    __half2 h = __floats2half2_rn(a, b);
    return *reinterpret_cast<uint32_t*>(&h);
}
__device__ __forceinline__ float2 h2f(uint32_t u) {
    __half2 h = *reinterpret_cast<__half2*>(&u);
    return __half22float2(h);
}

// ---------------------------------------------------------------------------
// Kernel A: W fp32 -> fp16 convert (tiny: 128K elements)
// ---------------------------------------------------------------------------
__global__ __launch_bounds__(256)
void w_half_kernel(const float* __restrict__ src, __half* __restrict__ dst,
                   int n4)
{
    int i = blockIdx.x * blockDim.x + threadIdx.x;
    if (i >= n4) return;
    float4 v = ((const float4*)src)[i];
    uint2 o;
    o.x = pack_h2(v.x, v.y);
    o.y = pack_h2(v.z, v.w);
    ((uint2*)dst)[i] = o;
}

// ---------------------------------------------------------------------------
// Kernel B: mma.sync fp16 GEMM with bias, fp16 output.
// C[M,256] = half(A) * half(W)^T + bias.  Tile 128x256x32 (FULL N per block:
// A is read exactly once from DRAM).  256 threads, 2x4 warps, each 64x64.
// A converted in-kernel: LDG float4 (reg pipeline) -> cvt -> STS.
// ---------------------------------------------------------------------------
#define BM 128
#define BN 256
#define BK 32
#define SSTRIDE 80                  // smem row stride bytes (32 fp16 + pad)
#define A_TILE  (128 * SSTRIDE)     // 10240 B
#define B_TILE  (256 * SSTRIDE)     // 20480 B
#define A_O     0
#define B_O     A_TILE
#define BUF_B   (A_TILE + B_TILE)   // 30720 B
#define GEMM_SMEM (2 * BUF_B)       // 61440 B
#define NCHUNK  (N_FEAT / BK)       // 16

__global__ __launch_bounds__(256, 1)
void gemm_mma_kernel(const float* __restrict__ A,
                     const __half* __restrict__ Bh,
                     const float* __restrict__ bias,
                     __half* __restrict__ C, int M)
{
    extern __shared__ __align__(128) char smem[];
    const uint32_t sb = smem_to_u32(smem);

    const int tid    = threadIdx.x;
    const int lane   = tid & 31;
    const int wid    = tid >> 5;
    const int warp_m = wid >> 2;          // 0..1  (64-row slab)
    const int warp_n = wid & 3;           // 0..3  (64-col slab)
    const int tile_row = blockIdx.x * BM;

    // A-load mapping: 8 threads cover one 128B (32-float) row segmentwise
    const int a_seg = tid & 7;
    const int a_r0  = tid >> 3;           // rows a_r0 + 32*i, i=0..3

    float acc[4][8][4];
#pragma unroll
    for (int a = 0; a < 4; a++)
#pragma unroll
        for (int b = 0; b < 8; b++)
#pragma unroll
            for (int c = 0; c < 4; c++) acc[a][b][c] = 0.f;

    float4 aPre[4];

    auto ldg_a = [&](int c) {
#pragma unroll
        for (int i = 0; i < 4; i++) {
            int gr = tile_row + a_r0 + 32 * i;
            if (gr >= M) gr = M - 1;
            aPre[i] = __ldg((const float4*)(A + (size_t)gr * N_FEAT
                                            + c * BK + a_seg * 4));
        }
    };
    auto sts_a = [&](int buf) {
#pragma unroll
        for (int i = 0; i < 4; i++) {
            uint2 o;
            o.x = pack_h2(aPre[i].x, aPre[i].y);
            o.y = pack_h2(aPre[i].z, aPre[i].w);
            *(uint2*)(smem + buf * BUF_B + A_O
                      + (a_r0 + 32 * i) * SSTRIDE + a_seg * 8) = o;
        }
    };
    auto issue_b = [&](int c) {
        const uint32_t b = sb + (c & 1) * BUF_B + B_O;
#pragma unroll
        for (int t = 0; t < 4; t++) {
            int idx = t * 256 + tid;          // 0..1023
            int r = idx >> 2, s = idx & 3;    // row 0..255, 16B seg 0..3
            size_t go = (size_t)r * N_FEAT + c * BK + s * 8;
            cp_async16(b + r * SSTRIDE + s * 16, Bh + go);
        }
        CP_COMMIT();
    };

    auto compute = [&](int buf) {
        const uint32_t base = sb + buf * BUF_B;
        const int arow = warp_m * 64 + (lane & 15);
        const int brow = warp_n * 64 + (lane & 7) + ((lane >> 4) << 3);
#pragma unroll
        for (int kk = 0; kk < 2; kk++) {
            const int k0 = kk * 16;
            const int acol2 = (k0 + ((lane >> 4) << 3)) * 2;
            const int bcol2 = (k0 + (((lane >> 3) & 1) << 3)) * 2;
            uint32_t aF[4][4], bF[8][2];
#pragma unroll
            for (int mt = 0; mt < 4; mt++)
                ldm_x4(aF[mt], base + A_O
                       + (uint32_t)(arow + mt * 16) * SSTRIDE + acol2);
#pragma unroll
            for (int h = 0; h < 4; h++) {
                uint32_t r[4];
                ldm_x4(r, base + B_O
                       + (uint32_t)(brow + h * 16) * SSTRIDE + bcol2);
                bF[h * 2][0]     = r[0]; bF[h * 2][1]     = r[1];
                bF[h * 2 + 1][0] = r[2]; bF[h * 2 + 1][1] = r[3];
            }
#pragma unroll
            for (int mt = 0; mt < 4; mt++)
#pragma unroll
                for (int nt = 0; nt < 8; nt++)
                    mma16816(acc[mt][nt], aF[mt], bF[nt]);
        }
    };

    // ---- pipeline prologue ----
    ldg_a(0);
    sts_a(0);
    issue_b(0);

    for (int c = 0; c < NCHUNK; c++) {
        if (c + 1 < NCHUNK) {
            ldg_a(c + 1);           // overlap LDG latency with compute below
            issue_b(c + 1);
            CP_WAIT(1);
        } else {
            CP_WAIT(0);
        }
        __syncthreads();            // chunk c A STS + B cp.async visible
        compute(c & 1);
        __syncthreads();            // done reading buf c
        if (c + 1 < NCHUNK)
            sts_a((c + 1) & 1);     // fill other buffer's A region
    }

    // ---- epilogue: bias add + fp16 store ----
    const int g  = lane >> 2;
    const int tg = lane & 3;
#pragma unroll
    for (int mt = 0; mt < 4; mt++) {
        const int r0 = tile_row + warp_m * 64 + mt * 16 + g;
#pragma unroll
        for (int half = 0; half < 2; half++) {
            const int row = r0 + half * 8;
            if (row >= M) continue;
            __half* cp = C + (size_t)row * N_HID;
#pragma unroll
            for (int nt = 0; nt < 8; nt++) {
                const int col = warp_n * 64 + nt * 8 + tg * 2;
                float ox = acc[mt][nt][half * 2 + 0] + __ldg(bias + col);
                float oy = acc[mt][nt][half * 2 + 1] + __ldg(bias + col + 1);
                *(uint32_t*)(cp + col) = pack_h2(ox, oy);
            }
        }
    }
}

// ---------------------------------------------------------------------------
// CSR build: count -> 2-level exclusive scan -> positioned scatter
// ---------------------------------------------------------------------------
__global__ __launch_bounds__(256)
void csr_count_kernel(const int* __restrict__ rows, int E)
{
    int e = blockIdx.x * blockDim.x + threadIdx.x;
    if (e < E) atomicAdd(&g_cnt[rows[e]], 1);
}

__global__ __launch_bounds__(SCAN_BLK)
void scan1_kernel()
{
    __shared__ int s[SCAN_BLK];
    const int tid = threadIdx.x;
    const int i = blockIdx.x * SCAN_BLK + tid;
    int v = (i < N_NODES) ? g_cnt[i] : 0;
    s[tid] = v;
    __syncthreads();
#pragma unroll
    for (int off = 1; off < SCAN_BLK; off <<= 1) {
        int t = (tid >= off) ? s[tid - off] : 0;
        __syncthreads();
        s[tid] += t;
        __syncthreads();
    }
    if (i < N_NODES) g_rowptr[i] = s[tid] - v;   // exclusive
    if (tid == SCAN_BLK - 1) g_blocksum[blockIdx.x] = s[tid];
}

__global__ __launch_bounds__(128)
void scan2_kernel()
{
    __shared__ int s[128];
    const int tid = threadIdx.x;
    int v = (tid < NB_SCAN) ? g_blocksum[tid] : 0;
    s[tid] = v;
    __syncthreads();
#pragma unroll
    for (int off = 1; off < 128; off <<= 1) {
        int t = (tid >= off) ? s[tid - off] : 0;
        __syncthreads();
        s[tid] += t;
        __syncthreads();
    }
    if (tid < NB_SCAN) g_blocksum[tid] = s[tid] - v;  // exclusive
}

__global__ __launch_bounds__(SCAN_BLK)
void scan3_kernel(int E)
{
    const int i = blockIdx.x * SCAN_BLK + threadIdx.x;
    if (i < N_NODES) g_rowptr[i] += g_blocksum[blockIdx.x];
    if (i == 0) g_rowptr[N_NODES] = E;
}

__global__ __launch_bounds__(256)
void csr_scatter_kernel(const int* __restrict__ rows,
                        const int* __restrict__ cols,
                        const float* __restrict__ vals, int E)
{
    int e = blockIdx.x * blockDim.x + threadIdx.x;
    if (e >= E) return;
    int r = rows[e];
    int pos = g_rowptr[r] + atomicAdd(&g_tmp[r], 1);
    g_sedge[pos] = make_int2(cols[e], __float_as_int(vals[e]));
}

// ---------------------------------------------------------------------------
// Kernel C: CSR SpMM (fp16 h) + fused PReLU. One warp per output row; each
// lane owns 8 features (one uint4 = 8 fp16 per gather), fp32 accumulation,
// streaming write-once stores.
// ---------------------------------------------------------------------------
__device__ __forceinline__ void stcs_v4(float* p, float4 v) {
    asm volatile("st.global.cs.v4.f32 [%0], {%1,%2,%3,%4};"
                 :: "l"(p), "f"(v.x), "f"(v.y), "f"(v.z), "f"(v.w) : "memory");
}

__device__ __forceinline__ void fma8(float4& a0, float4& a1, float v,
                                     uint4 raw)
{
    float2 f0 = h2f(raw.x), f1 = h2f(raw.y);
    float2 f2 = h2f(raw.z), f3 = h2f(raw.w);
    a0.x = fmaf(v, f0.x, a0.x); a0.y = fmaf(v, f0.y, a0.y);
    a0.z = fmaf(v, f1.x, a0.z); a0.w = fmaf(v, f1.y, a0.w);
    a1.x = fmaf(v, f2.x, a1.x); a1.y = fmaf(v, f2.y, a1.y);
    a1.z = fmaf(v, f3.x, a1.z); a1.w = fmaf(v, f3.y, a1.w);
}

__global__ __launch_bounds__(256)
void spmm_csr_prelu(float* __restrict__ out,
                    const float* __restrict__ alpha_p)
{
    const int warp = (blockIdx.x * blockDim.x + threadIdx.x) >> 5;
    const int lane = threadIdx.x & 31;
    if (warp >= N_NODES) return;

    const int start = g_rowptr[warp];
    const int end   = g_rowptr[warp + 1];

    float4 acc0 = make_float4(0.f, 0.f, 0.f, 0.f);
    float4 acc1 = make_float4(0.f, 0.f, 0.f, 0.f);

    int e = start;
    for (; e + 1 < end; e += 2) {
        int2 e0 = __ldcs(&g_sedge[e]);
        int2 e1 = __ldcs(&g_sedge[e + 1]);
        const float v0 = __int_as_float(e0.y);
        const float v1 = __int_as_float(e1.y);
        uint4 r0 = __ldg((const uint4*)(g_hh + (size_t)e0.x * N_HID) + lane);
        uint4 r1 = __ldg((const uint4*)(g_hh + (size_t)e1.x * N_HID) + lane);
        fma8(acc0, acc1, v0, r0);
        fma8(acc0, acc1, v1, r1);
    }
    if (e < end) {
        int2 e0 = __ldcs(&g_sedge[e]);
        const float v0 = __int_as_float(e0.y);
        uint4 r0 = __ldg((const uint4*)(g_hh + (size_t)e0.x * N_HID) + lane);
        fma8(acc0, acc1, v0, r0);
    }

    const float alpha = __ldg(alpha_p);
    acc0.x = acc0.x >= 0.f ? acc0.x : alpha * acc0.x;
    acc0.y = acc0.y >= 0.f ? acc0.y : alpha * acc0.y;
    acc0.z = acc0.z >= 0.f ? acc0.z : alpha * acc0.z;
    acc0.w = acc0.w >= 0.f ? acc0.w : alpha * acc0.w;
    acc1.x = acc1.x >= 0.f ? acc1.x : alpha * acc1.x;
    acc1.y = acc1.y >= 0.f ? acc1.y : alpha * acc1.y;
    acc1.z = acc1.z >= 0.f ? acc1.z : alpha * acc1.z;
    acc1.w = acc1.w >= 0.f ? acc1.w : alpha * acc1.w;

    float* dst = out + (size_t)warp * N_HID + lane * 8;
    stcs_v4(dst,     acc0);
    stcs_v4(dst + 4, acc1);
}

// ---------------------------------------------------------------------------
// Launch
// ---------------------------------------------------------------------------
extern "C" void kernel_launch(void* const* d_in, const int* in_sizes, int n_in,
                              void* d_out, int out_size)
{
    const float* x     = (const float*)d_in[0];
    const int*   rows  = (const int*)  d_in[1];
    const int*   cols  = (const int*)  d_in[2];
    const float* vals  = (const float*)d_in[3];
    const float* W     = (const float*)d_in[4];
    const float* b     = (const float*)d_in[5];
    const float* alpha = (const float*)d_in[6];

    float* out = (float*)d_out;
    const int E = in_sizes[1];

    __half *hh, *wh;
    cudaGetSymbolAddress((void**)&hh, g_hh);
    cudaGetSymbolAddress((void**)&wh, g_wh);

    int *cntp, *tmpp;
    cudaGetSymbolAddress((void**)&cntp, g_cnt);
    cudaGetSymbolAddress((void**)&tmpp, g_tmp);

    // --- CSR build (independent of GEMM) ---
    cudaMemsetAsync(cntp, 0, N_NODES * sizeof(int));
    cudaMemsetAsync(tmpp, 0, N_NODES * sizeof(int));
    csr_count_kernel<<<(E + 255) / 256, 256>>>(rows, E);
    scan1_kernel<<<NB_SCAN, SCAN_BLK>>>();
    scan2_kernel<<<1, 128>>>();
    scan3_kernel<<<NB_SCAN, SCAN_BLK>>>(E);
    csr_scatter_kernel<<<(E + 255) / 256, 256>>>(rows, cols, vals, E);

    // --- W fp16 convert (tiny) ---
    {
        int n4w = (N_HID * N_FEAT) / 4;
        w_half_kernel<<<(n4w + 255) / 256, 256>>>(W, wh, n4w);
    }

    // --- fp16 HMMA GEMM with bias -> g_hh (A read once; fp16 output) ---
    cudaFuncSetAttribute(gemm_mma_kernel,
                         cudaFuncAttributeMaxDynamicSharedMemorySize, GEMM_SMEM);
    dim3 ggrid((N_NODES + BM - 1) / BM, 1);
    gemm_mma_kernel<<<ggrid, 256, GEMM_SMEM>>>(x, wh, b, hh, N_NODES);

    // --- CSR SpMM (fp16 gather) + fused PReLU (atomic-free, write-once) ---
    int nwarps_blocks = (N_NODES * 32 + 255) / 256;
    spmm_csr_prelu<<<nwarps_blocks, 256>>>(out, alpha);
}

// round 10
// speedup vs baseline: 5.4638x; 1.0670x over previous
#include <cuda_runtime.h>
#include <cuda_bf16.h>
#include <cuda_fp16.h>
#include <cstdint>

// Problem constants (fixed by the dataset)
#define N_NODES    100000
#define N_FEAT     512
#define N_HID      256
#define MAX_E      3276800      // dataset E = 3,200,000 (+ margin)

// ---------------------------------------------------------------------------
// Static device scratch (no allocations allowed)
// ---------------------------------------------------------------------------
__device__ __align__(16) __half g_hh[(size_t)N_NODES * N_HID];      // 51.2 MB
__device__ __align__(16) __half g_wh[(size_t)N_HID * N_FEAT];       // 256 KB

// CSR build scratch
__device__ int  g_cnt[N_NODES];
__device__ int  g_tmp[N_NODES];
__device__ int  g_rowptr[N_NODES + 1];
__device__ int  g_blocksum[128];
__device__ __align__(8) int2 g_sedge[MAX_E];   // {col, val-as-int}

#define SCAN_BLK 1024
#define NB_SCAN  ((N_NODES + SCAN_BLK - 1) / SCAN_BLK)   // 98

// ---------------------------------------------------------------------------
// Baseline-PTX helpers (plain sm_80+; harness targets compute_103 w/o 'a')
// ---------------------------------------------------------------------------
__device__ __forceinline__ uint32_t smem_to_u32(const void* smem_ptr) {
    uint32_t addr;
    asm("{ .reg .u64 tmp; cvta.to.shared.u64 tmp, %1; cvt.u32.u64 %0, tmp; }"
        : "=r"(addr) : "l"(smem_ptr));
    return addr;
}

__device__ __forceinline__ void cp_async16(uint32_t saddr, const void* gptr) {
    asm volatile("cp.async.cg.shared.global [%0], [%1], 16;"
                 :: "r"(saddr), "l"(gptr));
}
#define CP_COMMIT()  asm volatile("cp.async.commit_group;")
#define CP_WAIT(N)   asm volatile("cp.async.wait_group %0;" :: "n"(N))

__device__ __forceinline__ void ldm_x4(uint32_t* r, uint32_t addr) {
    asm volatile("ldmatrix.sync.aligned.m8n8.x4.shared.b16 {%0,%1,%2,%3}, [%4];"
                 : "=r"(r[0]), "=r"(r[1]), "=r"(r[2]), "=r"(r[3]) : "r"(addr));
}

// HMMA m16n8k16 fp16 -> fp32, accumulate in place
__device__ __forceinline__ void mma16816(float* d, const uint32_t* a,
                                         const uint32_t* b) {
    asm volatile(
        "mma.sync.aligned.m16n8k16.row.col.f32.f16.f16.f32 "
        "{%0,%1,%2,%3}, {%4,%5,%6,%7}, {%8,%9}, {%0,%1,%2,%3};"
        : "+f"(d[0]), "+f"(d[1]), "+f"(d[2]), "+f"(d[3])
        : "r"(a[0]), "r"(a[1]), "r"(a[2]), "r"(a[3]),
          "r"(b[0]), "r"(b[1]));
}

__device__ __forceinline__ uint32_t pack_h2(float a, float b) {
    __half2 h = __floats2half2_rn(a, b);
    return *reinterpret_cast<uint32_t*>(&h);
}
__device__ __forceinline__ float2 h2f(uint32_t u) {
    __half2 h = *reinterpret_cast<__half2*>(&u);
    return __half22float2(h);
}

// ---------------------------------------------------------------------------
// Kernel A: W fp32 -> fp16 convert (tiny: 128K elements)
// ---------------------------------------------------------------------------
__global__ __launch_bounds__(256)
void w_half_kernel(const float* __restrict__ src, __half* __restrict__ dst,
                   int n4)
{
    int i = blockIdx.x * blockDim.x + threadIdx.x;
    if (i >= n4) return;
    float4 v = ((const float4*)src)[i];
    uint2 o;
    o.x = pack_h2(v.x, v.y);
    o.y = pack_h2(v.z, v.w);
    ((uint2*)dst)[i] = o;
}

// ---------------------------------------------------------------------------
// Kernel B: mma.sync fp16 GEMM with bias, fp16 output.
// C[M,256] = half(A) * half(W)^T + bias.  Tile 128x256x32 (FULL N per block:
// A is read exactly once from DRAM).  256 threads, 2x4 warps, each 64x64.
// A converted in-kernel: LDG float4 (reg pipeline) -> cvt -> STS.
// ---------------------------------------------------------------------------
#define BM 128
#define BN 256
#define BK 32
#define SSTRIDE 80                  // smem row stride bytes (32 fp16 + pad)
#define A_TILE  (128 * SSTRIDE)     // 10240 B
#define B_TILE  (256 * SSTRIDE)     // 20480 B
#define A_O     0
#define B_O     A_TILE
#define BUF_B   (A_TILE + B_TILE)   // 30720 B
#define GEMM_SMEM (2 * BUF_B)       // 61440 B
#define NCHUNK  (N_FEAT / BK)       // 16

__global__ __launch_bounds__(256, 1)
void gemm_mma_kernel(const float* __restrict__ A,
                     const __half* __restrict__ Bh,
                     const float* __restrict__ bias,
                     __half* __restrict__ C, int M)
{
    extern __shared__ __align__(128) char smem[];
    const uint32_t sb = smem_to_u32(smem);

    const int tid    = threadIdx.x;
    const int lane   = tid & 31;
    const int wid    = tid >> 5;
    const int warp_m = wid >> 2;          // 0..1  (64-row slab)
    const int warp_n = wid & 3;           // 0..3  (64-col slab)
    const int tile_row = blockIdx.x * BM;

    // A-load mapping: 8 threads cover one 128B (32-float) row segmentwise
    const int a_seg = tid & 7;
    const int a_r0  = tid >> 3;           // rows a_r0 + 32*i, i=0..3

    float acc[4][8][4];
#pragma unroll
    for (int a = 0; a < 4; a++)
#pragma unroll
        for (int b = 0; b < 8; b++)
#pragma unroll
            for (int c = 0; c < 4; c++) acc[a][b][c] = 0.f;

    float4 aPre[4];

    auto ldg_a = [&](int c) {
#pragma unroll
        for (int i = 0; i < 4; i++) {
            int gr = tile_row + a_r0 + 32 * i;
            if (gr >= M) gr = M - 1;
            aPre[i] = __ldg((const float4*)(A + (size_t)gr * N_FEAT
                                            + c * BK + a_seg * 4));
        }
    };
    auto sts_a = [&](int buf) {
#pragma unroll
        for (int i = 0; i < 4; i++) {
            uint2 o;
            o.x = pack_h2(aPre[i].x, aPre[i].y);
            o.y = pack_h2(aPre[i].z, aPre[i].w);
            *(uint2*)(smem + buf * BUF_B + A_O
                      + (a_r0 + 32 * i) * SSTRIDE + a_seg * 8) = o;
        }
    };
    auto issue_b = [&](int c) {
        const uint32_t b = sb + (c & 1) * BUF_B + B_O;
#pragma unroll
        for (int t = 0; t < 4; t++) {
            int idx = t * 256 + tid;          // 0..1023
            int r = idx >> 2, s = idx & 3;    // row 0..255, 16B seg 0..3
            size_t go = (size_t)r * N_FEAT + c * BK + s * 8;
            cp_async16(b + r * SSTRIDE + s * 16, Bh + go);
        }
        CP_COMMIT();
    };

    auto compute = [&](int buf) {
        const uint32_t base = sb + buf * BUF_B;
        const int arow = warp_m * 64 + (lane & 15);
        const int brow = warp_n * 64 + (lane & 7) + ((lane >> 4) << 3);
#pragma unroll
        for (int kk = 0; kk < 2; kk++) {
            const int k0 = kk * 16;
            const int acol2 = (k0 + ((lane >> 4) << 3)) * 2;
            const int bcol2 = (k0 + (((lane >> 3) & 1) << 3)) * 2;
            uint32_t aF[4][4], bF[8][2];
#pragma unroll
            for (int mt = 0; mt < 4; mt++)
                ldm_x4(aF[mt], base + A_O
                       + (uint32_t)(arow + mt * 16) * SSTRIDE + acol2);
#pragma unroll
            for (int h = 0; h < 4; h++) {
                uint32_t r[4];
                ldm_x4(r, base + B_O
                       + (uint32_t)(brow + h * 16) * SSTRIDE + bcol2);
                bF[h * 2][0]     = r[0]; bF[h * 2][1]     = r[1];
                bF[h * 2 + 1][0] = r[2]; bF[h * 2 + 1][1] = r[3];
            }
#pragma unroll
            for (int mt = 0; mt < 4; mt++)
#pragma unroll
                for (int nt = 0; nt < 8; nt++)
                    mma16816(acc[mt][nt], aF[mt], bF[nt]);
        }
    };

    // ---- pipeline prologue ----
    ldg_a(0);
    sts_a(0);
    issue_b(0);

    for (int c = 0; c < NCHUNK; c++) {
        if (c + 1 < NCHUNK) {
            ldg_a(c + 1);           // overlap LDG latency with compute below
            issue_b(c + 1);
            CP_WAIT(1);
        } else {
            CP_WAIT(0);
        }
        __syncthreads();            // chunk c A STS + B cp.async visible
        compute(c & 1);
        __syncthreads();            // done reading buf c
        if (c + 1 < NCHUNK)
            sts_a((c + 1) & 1);     // fill other buffer's A region
    }

    // ---- epilogue: bias add + fp16 store ----
    const int g  = lane >> 2;
    const int tg = lane & 3;
#pragma unroll
    for (int mt = 0; mt < 4; mt++) {
        const int r0 = tile_row + warp_m * 64 + mt * 16 + g;
#pragma unroll
        for (int half = 0; half < 2; half++) {
            const int row = r0 + half * 8;
            if (row >= M) continue;
            __half* cp = C + (size_t)row * N_HID;
#pragma unroll
            for (int nt = 0; nt < 8; nt++) {
                const int col = warp_n * 64 + nt * 8 + tg * 2;
                float ox = acc[mt][nt][half * 2 + 0] + __ldg(bias + col);
                float oy = acc[mt][nt][half * 2 + 1] + __ldg(bias + col + 1);
                *(uint32_t*)(cp + col) = pack_h2(ox, oy);
            }
        }
    }
}

// ---------------------------------------------------------------------------
// CSR build: count -> 2-level exclusive scan -> positioned scatter
// ---------------------------------------------------------------------------
__global__ __launch_bounds__(256)
void csr_count_kernel(const int* __restrict__ rows, int E)
{
    int e = blockIdx.x * blockDim.x + threadIdx.x;
    if (e < E) atomicAdd(&g_cnt[rows[e]], 1);
}

__global__ __launch_bounds__(SCAN_BLK)
void scan1_kernel()
{
    __shared__ int s[SCAN_BLK];
    const int tid = threadIdx.x;
    const int i = blockIdx.x * SCAN_BLK + tid;
    int v = (i < N_NODES) ? g_cnt[i] : 0;
    s[tid] = v;
    __syncthreads();
#pragma unroll
    for (int off = 1; off < SCAN_BLK; off <<= 1) {
        int t = (tid >= off) ? s[tid - off] : 0;
        __syncthreads();
        s[tid] += t;
        __syncthreads();
    }
    if (i < N_NODES) g_rowptr[i] = s[tid] - v;   // exclusive
    if (tid == SCAN_BLK - 1) g_blocksum[blockIdx.x] = s[tid];
}

__global__ __launch_bounds__(128)
void scan2_kernel()
{
    __shared__ int s[128];
    const int tid = threadIdx.x;
    int v = (tid < NB_SCAN) ? g_blocksum[tid] : 0;
    s[tid] = v;
    __syncthreads();
#pragma unroll
    for (int off = 1; off < 128; off <<= 1) {
        int t = (tid >= off) ? s[tid - off] : 0;
        __syncthreads();
        s[tid] += t;
        __syncthreads();
    }
    if (tid < NB_SCAN) g_blocksum[tid] = s[tid] - v;  // exclusive
}

__global__ __launch_bounds__(SCAN_BLK)
void scan3_kernel(int E)
{
    const int i = blockIdx.x * SCAN_BLK + threadIdx.x;
    if (i < N_NODES) g_rowptr[i] += g_blocksum[blockIdx.x];
    if (i == 0) g_rowptr[N_NODES] = E;
}

__global__ __launch_bounds__(256)
void csr_scatter_kernel(const int* __restrict__ rows,
                        const int* __restrict__ cols,
                        const float* __restrict__ vals, int E)
{
    int e = blockIdx.x * blockDim.x + threadIdx.x;
    if (e >= E) return;
    int r = rows[e];
    int pos = g_rowptr[r] + atomicAdd(&g_tmp[r], 1);
    g_sedge[pos] = make_int2(cols[e], __float_as_int(vals[e]));
}

// ---------------------------------------------------------------------------
// Kernel C: CSR SpMM (fp16 h) + fused PReLU. One warp per output row; each
// lane owns 8 features (one uint4 = 8 fp16 per gather), fp32 accumulation,
// streaming write-once stores.
// ---------------------------------------------------------------------------
__device__ __forceinline__ void stcs_v4(float* p, float4 v) {
    asm volatile("st.global.cs.v4.f32 [%0], {%1,%2,%3,%4};"
                 :: "l"(p), "f"(v.x), "f"(v.y), "f"(v.z), "f"(v.w) : "memory");
}

__device__ __forceinline__ void fma8(float4& a0, float4& a1, float v,
                                     uint4 raw)
{
    float2 f0 = h2f(raw.x), f1 = h2f(raw.y);
    float2 f2 = h2f(raw.z), f3 = h2f(raw.w);
    a0.x = fmaf(v, f0.x, a0.x); a0.y = fmaf(v, f0.y, a0.y);
    a0.z = fmaf(v, f1.x, a0.z); a0.w = fmaf(v, f1.y, a0.w);
    a1.x = fmaf(v, f2.x, a1.x); a1.y = fmaf(v, f2.y, a1.y);
    a1.z = fmaf(v, f3.x, a1.z); a1.w = fmaf(v, f3.y, a1.w);
}

__global__ __launch_bounds__(256)
void spmm_csr_prelu(float* __restrict__ out,
                    const float* __restrict__ alpha_p)
{
    const int warp = (blockIdx.x * blockDim.x + threadIdx.x) >> 5;
    const int lane = threadIdx.x & 31;
    if (warp >= N_NODES) return;

    const int start = g_rowptr[warp];
    const int end   = g_rowptr[warp + 1];

    float4 acc0 = make_float4(0.f, 0.f, 0.f, 0.f);
    float4 acc1 = make_float4(0.f, 0.f, 0.f, 0.f);

    int e = start;
    for (; e + 1 < end; e += 2) {
        int2 e0 = __ldcs(&g_sedge[e]);
        int2 e1 = __ldcs(&g_sedge[e + 1]);
        const float v0 = __int_as_float(e0.y);
        const float v1 = __int_as_float(e1.y);
        uint4 r0 = __ldg((const uint4*)(g_hh + (size_t)e0.x * N_HID) + lane);
        uint4 r1 = __ldg((const uint4*)(g_hh + (size_t)e1.x * N_HID) + lane);
        fma8(acc0, acc1, v0, r0);
        fma8(acc0, acc1, v1, r1);
    }
    if (e < end) {
        int2 e0 = __ldcs(&g_sedge[e]);
        const float v0 = __int_as_float(e0.y);
        uint4 r0 = __ldg((const uint4*)(g_hh + (size_t)e0.x * N_HID) + lane);
        fma8(acc0, acc1, v0, r0);
    }

    const float alpha = __ldg(alpha_p);
    acc0.x = acc0.x >= 0.f ? acc0.x : alpha * acc0.x;
    acc0.y = acc0.y >= 0.f ? acc0.y : alpha * acc0.y;
    acc0.z = acc0.z >= 0.f ? acc0.z : alpha * acc0.z;
    acc0.w = acc0.w >= 0.f ? acc0.w : alpha * acc0.w;
    acc1.x = acc1.x >= 0.f ? acc1.x : alpha * acc1.x;
    acc1.y = acc1.y >= 0.f ? acc1.y : alpha * acc1.y;
    acc1.z = acc1.z >= 0.f ? acc1.z : alpha * acc1.z;
    acc1.w = acc1.w >= 0.f ? acc1.w : alpha * acc1.w;

    float* dst = out + (size_t)warp * N_HID + lane * 8;
    stcs_v4(dst,     acc0);
    stcs_v4(dst + 4, acc1);
}

// ---------------------------------------------------------------------------
// Launch: fork/join so the CSR chain overlaps the convert+GEMM chain.
//   main stream:  W convert -> GEMM ----------------.
//   side stream:  memsets -> count -> scans -> scatter --> join -> SpMM
// Stream/event create+destroy are host-side (no device allocation) and follow
// the documented cross-stream capture fork pattern.
// ---------------------------------------------------------------------------
extern "C" void kernel_launch(void* const* d_in, const int* in_sizes, int n_in,
                              void* d_out, int out_size)
{
    const float* x     = (const float*)d_in[0];
    const int*   rows  = (const int*)  d_in[1];
    const int*   cols  = (const int*)  d_in[2];
    const float* vals  = (const float*)d_in[3];
    const float* W     = (const float*)d_in[4];
    const float* b     = (const float*)d_in[5];
    const float* alpha = (const float*)d_in[6];

    float* out = (float*)d_out;
    const int E = in_sizes[1];

    __half *hh, *wh;
    cudaGetSymbolAddress((void**)&hh, g_hh);
    cudaGetSymbolAddress((void**)&wh, g_wh);

    int *cntp, *tmpp;
    cudaGetSymbolAddress((void**)&cntp, g_cnt);
    cudaGetSymbolAddress((void**)&tmpp, g_tmp);

    cudaStream_t s1;
    cudaStreamCreateWithFlags(&s1, cudaStreamNonBlocking);
    cudaEvent_t evFork, evJoin;
    cudaEventCreateWithFlags(&evFork, cudaEventDisableTiming);
    cudaEventCreateWithFlags(&evJoin, cudaEventDisableTiming);

    // ---- fork: side stream branches off the (possibly capturing) stream ----
    cudaEventRecord(evFork, 0);
    cudaStreamWaitEvent(s1, evFork, 0);

    // ---- side stream: CSR build chain ----
    cudaMemsetAsync(cntp, 0, N_NODES * sizeof(int), s1);
    cudaMemsetAsync(tmpp, 0, N_NODES * sizeof(int), s1);
    csr_count_kernel<<<(E + 255) / 256, 256, 0, s1>>>(rows, E);
    scan1_kernel<<<NB_SCAN, SCAN_BLK, 0, s1>>>();
    scan2_kernel<<<1, 128, 0, s1>>>();
    scan3_kernel<<<NB_SCAN, SCAN_BLK, 0, s1>>>(E);
    csr_scatter_kernel<<<(E + 255) / 256, 256, 0, s1>>>(rows, cols, vals, E);
    cudaEventRecord(evJoin, s1);

    // ---- main stream: W convert + GEMM ----
    {
        int n4w = (N_HID * N_FEAT) / 4;
        w_half_kernel<<<(n4w + 255) / 256, 256>>>(W, wh, n4w);
    }
    cudaFuncSetAttribute(gemm_mma_kernel,
                         cudaFuncAttributeMaxDynamicSharedMemorySize, GEMM_SMEM);
    dim3 ggrid((N_NODES + BM - 1) / BM, 1);
    gemm_mma_kernel<<<ggrid, 256, GEMM_SMEM>>>(x, wh, b, hh, N_NODES);

    // ---- join, then SpMM needs both chains ----
    cudaStreamWaitEvent(0, evJoin, 0);
    int nwarps_blocks = (N_NODES * 32 + 255) / 256;
    spmm_csr_prelu<<<nwarps_blocks, 256>>>(out, alpha);

    cudaEventDestroy(evFork);
    cudaEventDestroy(evJoin);
    cudaStreamDestroy(s1);
}